// round 10
// baseline (speedup 1.0000x reference)
#include <cuda_runtime.h>
#include <cuda_fp16.h>
#include <cuda_bf16.h>
#include <cstdint>

#define N_TOTAL 2048
#define S_STEPS 32
#define DIM 256
#define PER_TS 1507328      // >= rows_max * rsU_max for realistic splits
#define ZSTRIDE 2056

// ---------------- scratch (device globals; no dynamic allocation) ------------
__device__ __align__(16) __half d_Mh[(size_t)S_STEPS * PER_TS];
__device__ __align__(16) unsigned char d_K8[(size_t)S_STEPS * PER_TS];
__device__ __align__(16) __nv_bfloat16 d_Xhi[(size_t)S_STEPS * N_TOTAL * DIM];
__device__ float d_norm[S_STEPS * N_TOTAL];
__device__ int   d_it[N_TOTAL], d_ic[N_TOTAL];
__device__ int   d_nt, d_nc;
__device__ float d_p;
__device__ float d_lam[S_STEPS], d_delta[S_STEPS];
__device__ __align__(16) float d_u[S_STEPS * ZSTRIDE];
__device__ __align__(16) float d_z[S_STEPS * ZSTRIDE];
__device__ float d_pmax[S_STEPS * 256];
__device__ float d_psum[S_STEPS * 256];
__device__ float d_pfin[256];

// ---------------- fast exp (Cephes, FMA pipe; args in [-8, 0]) ---------------
__device__ __forceinline__ float fexpf_(float x) {
    float z = fmaf(x, 1.4426950408889634f, 12582912.0f);
    float n = z - 12582912.0f;
    float r = fmaf(n, -0.693359375f, x);
    r = fmaf(n, 2.12194440e-4f, r);
    float p = 1.9875691500e-4f;
    p = fmaf(p, r, 1.3981999507e-3f);
    p = fmaf(p, r, 8.3334519073e-3f);
    p = fmaf(p, r, 4.1665795894e-2f);
    p = fmaf(p, r, 1.6666665459e-1f);
    p = fmaf(p, r, 5.0000001201e-1f);
    float e = fmaf(r * r, p, r) + 1.0f;
    int ni = (int)n;
    return __int_as_float(__float_as_int(e) + (ni << 23));
}

__device__ __forceinline__ uint32_t smem_u32(const void* p) {
    uint32_t a;
    asm("{ .reg .u64 t; cvta.to.shared.u64 t, %1; cvt.u32.u64 %0, t; }" : "=r"(a) : "l"(p));
    return a;
}

// 4 halves -> float4
__device__ __forceinline__ float4 h4_f4(uint2 w) {
    float2 a = __half22float2(*reinterpret_cast<__half2*>(&w.x));
    float2 b = __half22float2(*reinterpret_cast<__half2*>(&w.y));
    return make_float4(a.x, a.y, b.x, b.y);
}

// 4 u8 -> float4 (values 0..255; 1/255 scale folded into the vector operand)
__device__ __forceinline__ float4 u8x4_f4(uint32_t w) {
    return make_float4((float)(w & 0xffu), (float)((w >> 8) & 0xffu),
                       (float)((w >> 16) & 0xffu), (float)(w >> 24));
}

#define CLUSTER_SYNC() do { \
    asm volatile("barrier.cluster.arrive.aligned;" ::: "memory"); \
    asm volatile("barrier.cluster.wait.aligned;" ::: "memory"); } while (0)

#define LDSM4(R, addr) \
    asm volatile("ldmatrix.sync.aligned.m8n8.x4.shared.b16 {%0,%1,%2,%3}, [%4];" \
        : "=r"((R)[0]), "=r"((R)[1]), "=r"((R)[2]), "=r"((R)[3]) : "r"(addr))

#define MMA_BF16(C, A, b0_, b1_) \
    asm volatile("mma.sync.aligned.m16n8k16.row.col.f32.bf16.bf16.f32 " \
        "{%0,%1,%2,%3}, {%4,%5,%6,%7}, {%8,%9}, {%0,%1,%2,%3};" \
        : "+f"((C)[0]), "+f"((C)[1]), "+f"((C)[2]), "+f"((C)[3]) \
        : "r"((A)[0]), "r"((A)[1]), "r"((A)[2]), "r"((A)[3]), "r"(b0_), "r"(b1_))

#define CP_ASYNC16(smaddr, gptr, srcsz) \
    asm volatile("cp.async.cg.shared.global [%0], [%1], 16, %2;" \
        :: "r"(smaddr), "l"(gptr), "r"(srcsz))

// ---------------- 1) partition indices (deterministic, single block) ---------
__global__ void part_kernel(const int* __restrict__ t) {
    __shared__ int wcntT[64];
    __shared__ int wprefT[64], wprefC[64];
    int tid = threadIdx.x, lane = tid & 31, wid = tid >> 5;
    for (int c = wid; c < 64; c += 32) {
        int e = c * 32 + lane;
        int f = t[e] > 0;
        unsigned m = __ballot_sync(0xffffffffu, f);
        if (lane == 0) wcntT[c] = __popc(m);
    }
    __syncthreads();
    if (tid == 0) {
        int aT = 0;
        for (int c = 0; c < 64; c++) {
            wprefT[c] = aT;
            wprefC[c] = c * 32 - aT;
            aT += wcntT[c];
        }
        d_nt = aT;
        d_nc = N_TOTAL - aT;
        d_p  = (float)aT / (float)N_TOTAL;
    }
    __syncthreads();
    for (int c = wid; c < 64; c += 32) {
        int e = c * 32 + lane;
        int f = t[e] > 0;
        unsigned m  = __ballot_sync(0xffffffffu, f);
        unsigned lt = ((1u << lane) - 1u);
        if (f) d_it[wprefT[c] + __popc(m & lt)]  = e;
        else   d_ic[wprefC[c] + __popc(~m & lt)] = e;
    }
}

// ---------------- 2) gather rows -> bf16 + fp32 row norms --------------------
// grid (N_TOTAL, S), 64 threads
__global__ void gather_kernel(const float* __restrict__ enc) {
    int r = blockIdx.x, s = blockIdx.y, tid = threadIdx.x;
    int nt = d_nt;
    int src = (r < nt) ? d_it[r] : d_ic[r - nt];
    const float4* in = (const float4*)(enc + ((size_t)src * S_STEPS + s) * DIM);
    float4 v = in[tid];

    __nv_bfloat162 h01 = {__float2bfloat16_rn(v.x), __float2bfloat16_rn(v.y)};
    __nv_bfloat162 h23 = {__float2bfloat16_rn(v.z), __float2bfloat16_rn(v.w)};
    size_t base = ((size_t)s * N_TOTAL + r) * DIM + (size_t)tid * 4;
    uint2 hv = { *(unsigned*)&h01, *(unsigned*)&h23 };
    *(uint2*)(d_Xhi + base) = hv;

    float nrm = v.x * v.x + v.y * v.y + v.z * v.z + v.w * v.w;
    for (int o = 16; o; o >>= 1) nrm += __shfl_down_sync(0xffffffffu, nrm, o);
    __shared__ float sn[2];
    if ((tid & 31) == 0) sn[tid >> 5] = nrm;
    __syncthreads();
    if (tid == 0) d_norm[s * N_TOTAL + r] = sn[0] + sn[1];
}

// ---------------- 3) bf16 GEMM w/ cp.async double buffer ---------------------
// grid (16,16,S), 256 threads (8 warps: 2 m x 4 n), CTA tile 128x128
__global__ void __launch_bounds__(256, 2) gemm_kernel() {
    __shared__ __align__(16) unsigned char sm[41984];
    float* rbuf = (float*)(sm + 40960);

    int tid = threadIdx.x, lane = tid & 31, wid = tid >> 5;
    int wm = wid >> 2, wn = wid & 3;
    int s = blockIdx.z;
    int nt = d_nt, nc = d_nc;
    int i0 = blockIdx.y * 128, j0 = blockIdx.x * 128;
    int pidx = s * 256 + blockIdx.y * 16 + blockIdx.x;

    if (i0 >= nt || j0 >= nc) {
        if (tid == 0) { d_pmax[pidx] = 0.0f; d_psum[pidx] = 0.0f; }
        return;
    }

    uint32_t sb = smem_u32(sm);
    size_t Xbase = (size_t)s * N_TOTAL * DIM;

    int rowA[2], segA[2];
    bool va[2], vb[2];
    const __nv_bfloat16 *gA[2], *gB[2];
#pragma unroll
    for (int h = 0; h < 2; h++) {
        int idx = tid + h * 256;
        rowA[h] = idx >> 2; segA[h] = idx & 3;
        va[h] = (i0 + rowA[h]) < nt;
        vb[h] = (j0 + rowA[h]) < nc;
        int ra = va[h] ? (i0 + rowA[h]) : 0;
        int rb = vb[h] ? (j0 + rowA[h]) : 0;
        gA[h] = d_Xhi + Xbase + (size_t)ra * DIM + segA[h] * 8;
        gB[h] = d_Xhi + Xbase + (size_t)(nt + rb) * DIM + segA[h] * 8;
    }

    float c[4][4][4];
#pragma unroll
    for (int a = 0; a < 4; a++)
#pragma unroll
        for (int b = 0; b < 4; b++)
#pragma unroll
            for (int q = 0; q < 4; q++) c[a][b][q] = 0.0f;

    auto issue = [&](int chunk) {
        int k0 = chunk * 32;
        uint32_t bufo = (uint32_t)(chunk & 1) * 20480u;
#pragma unroll
        for (int h = 0; h < 2; h++) {
            uint32_t doff = (uint32_t)rowA[h] * 80 + (uint32_t)segA[h] * 16;
            CP_ASYNC16(sb + bufo + doff, gA[h] + k0, va[h] ? 16 : 0);
            CP_ASYNC16(sb + bufo + 10240 + doff, gB[h] + k0, vb[h] ? 16 : 0);
        }
        asm volatile("cp.async.commit_group;");
    };

    issue(0);

    for (int chunk = 0; chunk < 8; chunk++) {
        if (chunk < 7) {
            issue(chunk + 1);
            asm volatile("cp.async.wait_group 1;");
        } else {
            asm volatile("cp.async.wait_group 0;");
        }
        __syncthreads();

        uint32_t bufo = (uint32_t)(chunk & 1) * 20480u;
#pragma unroll
        for (int ks = 0; ks < 32; ks += 16) {
            uint32_t colb = (uint32_t)(ks + ((lane >> 4) << 3)) * 2;
            uint32_t ah[4][4], bh2[2][4];
#pragma unroll
            for (int mt = 0; mt < 4; mt++) {
                uint32_t addr = sb + bufo + (uint32_t)(wm * 64 + mt * 16 + (lane & 15)) * 80 + colb;
                LDSM4(ah[mt], addr);
            }
#pragma unroll
            for (int pp = 0; pp < 2; pp++) {
                uint32_t addr = sb + bufo + 10240 + (uint32_t)(wn * 32 + pp * 16 + (lane & 15)) * 80 + colb;
                LDSM4(bh2[pp], addr);
            }
#pragma unroll
            for (int mt = 0; mt < 4; mt++)
#pragma unroll
                for (int nn = 0; nn < 4; nn++) {
                    int pp = nn >> 1, od = nn & 1;
                    MMA_BF16(c[mt][nn], ah[mt], bh2[pp][od], bh2[pp][2 + od]);
                }
        }
        __syncthreads();
    }

    float* nbs = (float*)sm;
    for (int q = tid; q < 128; q += 256)
        nbs[q] = (j0 + q < nc) ? d_norm[s * N_TOTAL + nt + j0 + q] : 0.0f;
    __syncthreads();

    int rsU = (nc + 16) & ~15;
    float lmax = 0.0f, lsum = 0.0f;
#pragma unroll
    for (int mt = 0; mt < 4; mt++) {
        int gi0 = i0 + wm * 64 + mt * 16 + (lane >> 2);
        int gi1 = gi0 + 8;
        float na0 = (gi0 < nt) ? d_norm[s * N_TOTAL + gi0] : 0.0f;
        float na1 = (gi1 < nt) ? d_norm[s * N_TOTAL + gi1] : 0.0f;
#pragma unroll
        for (int nn = 0; nn < 4; nn++) {
            int lj = wn * 32 + nn * 8 + (lane & 3) * 2;
            int gj = j0 + lj;
            float nb0 = nbs[lj], nb1 = nbs[lj + 1];
            bool vj0 = gj < nc, vj1 = (gj + 1) < nc;
            float m00 = na0 + nb0 - 2.0f * c[mt][nn][0];
            float m01 = na0 + nb1 - 2.0f * c[mt][nn][1];
            float m10 = na1 + nb0 - 2.0f * c[mt][nn][2];
            float m11 = na1 + nb1 - 2.0f * c[mt][nn][3];
            if (gi0 < nt) {
                __half* Mr = d_Mh + (size_t)s * PER_TS + (size_t)gi0 * rsU + gj;
                if (vj0) { lmax = fmaxf(lmax, m00); lsum += m00; }
                if (vj1) { lmax = fmaxf(lmax, m01); lsum += m01; }
                if (vj0 && vj1) *(__half2*)Mr = __floats2half2_rn(m00, m01);
                else if (vj0)   *Mr = __float2half_rn(m00);
            }
            if (gi1 < nt) {
                __half* Mr = d_Mh + (size_t)s * PER_TS + (size_t)gi1 * rsU + gj;
                if (vj0) { lmax = fmaxf(lmax, m10); lsum += m10; }
                if (vj1) { lmax = fmaxf(lmax, m11); lsum += m11; }
                if (vj0 && vj1) *(__half2*)Mr = __floats2half2_rn(m10, m11);
                else if (vj0)   *Mr = __float2half_rn(m10);
            }
        }
    }

    rbuf[tid] = lmax; __syncthreads();
    for (int st = 128; st; st >>= 1) {
        if (tid < st) rbuf[tid] = fmaxf(rbuf[tid], rbuf[tid + st]);
        __syncthreads();
    }
    if (tid == 0) d_pmax[pidx] = rbuf[0];
    __syncthreads();
    rbuf[tid] = lsum; __syncthreads();
    for (int st = 128; st; st >>= 1) {
        if (tid < st) rbuf[tid] += rbuf[tid + st];
        __syncthreads();
    }
    if (tid == 0) d_psum[pidx] = rbuf[0];
}

// ---------------- 4) per-timestep stats --------------------------------------
__global__ void reduce_stats() {
    __shared__ float rb[256];
    int s = blockIdx.x, tid = threadIdx.x;
    float mv = d_pmax[s * 256 + tid];
    float sv = d_psum[s * 256 + tid];
    rb[tid] = mv; __syncthreads();
    for (int st = 128; st; st >>= 1) {
        if (tid < st) rb[tid] = fmaxf(rb[tid], rb[tid + st]);
        __syncthreads();
    }
    float mx = rb[0];
    __syncthreads();
    rb[tid] = sv; __syncthreads();
    for (int st = 128; st; st >>= 1) {
        if (tid < st) rb[tid] += rb[tid + st];
        __syncthreads();
    }
    if (tid == 0) {
        d_delta[s] = mx;
        d_lam[s] = ((float)d_nt * (float)d_nc) / rb[0];
    }
}

// ---------------- 5) persistent Sinkhorn: 32 clusters of 8 CTAs, 512 thr -----
// K stored as u8 (value*255); 1/255 folded into smem-staged u/z vectors.
__device__ __forceinline__ void colpass_f(
    const unsigned char* Kb, const float* ub, float* zb, float (*red)[164], float* svec,
    int ntp, int nc, int rsU, int Wc, int cbase, int lane, int wid, int tid,
    float bn, float bp)
{
    // stage u/255 into smem (one L2 pass)
    for (int i = tid; i < ntp; i += 512) svec[i] = __ldcg(ub + i) * (1.0f / 255.0f);
    __syncthreads();

    float acc[2][4] = {{0.f,0.f,0.f,0.f},{0.f,0.f,0.f,0.f}};
    int l4 = lane * 4;
    int jj0 = cbase + l4;
    int jj1 = jj0 + 128;
    bool v0 = (l4 < Wc) && (jj0 < rsU);
    bool v1 = (l4 + 128 < Wc) && (jj1 < rsU);
#pragma unroll 8
    for (int i = wid; i < ntp; i += 16) {
        float u = svec[i];
        const unsigned char* Kr = Kb + (size_t)i * rsU;
        if (v0) {
            float4 f = u8x4_f4(*(const uint32_t*)(Kr + jj0));
            acc[0][0] = fmaf(f.x, u, acc[0][0]);
            acc[0][1] = fmaf(f.y, u, acc[0][1]);
            acc[0][2] = fmaf(f.z, u, acc[0][2]);
            acc[0][3] = fmaf(f.w, u, acc[0][3]);
        }
        if (v1) {
            float4 f = u8x4_f4(*(const uint32_t*)(Kr + jj1));
            acc[1][0] = fmaf(f.x, u, acc[1][0]);
            acc[1][1] = fmaf(f.y, u, acc[1][1]);
            acc[1][2] = fmaf(f.z, u, acc[1][2]);
            acc[1][3] = fmaf(f.w, u, acc[1][3]);
        }
    }
    if (v0) {
#pragma unroll
        for (int q = 0; q < 4; q++) red[wid][l4 + q] = acc[0][q];
    }
    if (v1) {
#pragma unroll
        for (int q = 0; q < 4; q++) red[wid][128 + l4 + q] = acc[1][q];
    }
    __syncthreads();
    for (int cc = tid; cc < Wc; cc += 512) {
        int j = cbase + cc;
        if (j >= rsU) continue;
        float t = red[0][cc];
#pragma unroll
        for (int w = 1; w < 16; w++) t += red[w][cc];
        float zv = (j < nc) ? (bn / t) : ((j == nc) ? (bp / t) : 0.0f);
        __stcg(zb + j, zv);
    }
    __syncthreads();
}

__device__ __forceinline__ void rowpass_f(
    const unsigned char* Kb, float* ub, const float* zb, float* svec,
    int r0, int r1, int nt, int rsU, int lane, int wid, int tid, float an, float ap)
{
    // stage z/255 into smem (one L2 pass)
    for (int i = tid; i < rsU; i += 512) svec[i] = __ldcg(zb + i) * (1.0f / 255.0f);
    __syncthreads();

    for (int i = r0 + wid; i < r1; i += 32) {
        int i2 = i + 16;
        bool has2 = i2 < r1;
        const unsigned char* Kr1 = Kb + (size_t)i * rsU;
        const unsigned char* Kr2 = Kb + (size_t)(has2 ? i2 : i) * rsU;
        float a1 = 0.0f, a2 = 0.0f;
#pragma unroll 4
        for (int jj = lane * 4; jj < rsU; jj += 128) {
            float4 zv = *(const float4*)(svec + jj);
            float4 k1 = u8x4_f4(*(const uint32_t*)(Kr1 + jj));
            float4 k2 = u8x4_f4(*(const uint32_t*)(Kr2 + jj));
            a1 = fmaf(k1.x, zv.x, a1); a1 = fmaf(k1.y, zv.y, a1);
            a1 = fmaf(k1.z, zv.z, a1); a1 = fmaf(k1.w, zv.w, a1);
            a2 = fmaf(k2.x, zv.x, a2); a2 = fmaf(k2.y, zv.y, a2);
            a2 = fmaf(k2.z, zv.z, a2); a2 = fmaf(k2.w, zv.w, a2);
        }
#pragma unroll
        for (int o = 16; o; o >>= 1) {
            a1 += __shfl_down_sync(0xffffffffu, a1, o);
            a2 += __shfl_down_sync(0xffffffffu, a2, o);
        }
        if (lane == 0) {
            __stcg(ub + i, ((i < nt) ? an : ap) / a1);
            if (has2) __stcg(ub + i2, ((i2 < nt) ? an : ap) / a2);
        }
    }
    __syncthreads();
}

__global__ void __cluster_dims__(8, 1, 1) __launch_bounds__(512, 2) sink_cluster() {
    __shared__ float red[16][164];
    __shared__ float wsum[16];
    __shared__ __align__(16) float svec[2064];
    int bid = blockIdx.x;
    int s = bid >> 3, cr = bid & 7;
    int tid = threadIdx.x, lane = tid & 31, wid = tid >> 5;
    int nt = d_nt, nc = d_nc, ntp = nt + 1;
    int rsU = (nc + 16) & ~15;
    float lam = d_lam[s], delta = d_delta[s], p = d_p;
    float an = p / (float)nt, ap = 1.0f - p;
    float bn = (1.0f - p) / (float)nc, bp = p;
    __half* Mb = d_Mh + (size_t)s * PER_TS;
    unsigned char* Kb = d_K8 + (size_t)s * PER_TS;
    float* ub = d_u + s * ZSTRIDE;
    float* zb = d_z + s * ZSTRIDE;

    // ---- Phase A: build K u8 + M pads on row slice; init u slice ----
    int H = (ntp + 7) >> 3;
    int r0 = cr * H;
    int r1 = min(ntp, r0 + H);
    float kpad = fexpf_(-lam * delta) + 1e-6f;
    float kcorner = 1.0f + 1e-6f;
    for (int r = r0; r < r1; r++) {
        __half* Mw = Mb + (size_t)r * rsU;
        unsigned char* Kr = Kb + (size_t)r * rsU;
        for (int c = tid * 2; c < rsU; c += 1024) {
            float kk[2];
#pragma unroll
            for (int q = 0; q < 2; q++) {
                int cc = c + q;
                float kv;
                if (r < nt) {
                    if (cc < nc) {
                        kv = fexpf_(-lam * __half2float(Mw[cc])) + 1e-6f;
                    } else if (cc == nc) {
                        kv = kpad; Mw[cc] = __float2half_rn(delta);
                    } else {
                        kv = 0.0f; Mw[cc] = __float2half_rn(0.0f);
                    }
                } else {
                    if (cc < nc) { kv = kpad; Mw[cc] = __float2half_rn(delta); }
                    else if (cc == nc) { kv = kcorner; Mw[cc] = __float2half_rn(0.0f); }
                    else { kv = 0.0f; Mw[cc] = __float2half_rn(0.0f); }
                }
                kk[q] = kv;
            }
            unsigned q0 = __float2uint_rn(fminf(kk[0] * 255.0f, 255.0f));
            unsigned q1 = __float2uint_rn(fminf(kk[1] * 255.0f, 255.0f));
            *(unsigned short*)(Kr + c) = (unsigned short)(q0 | (q1 << 8));
        }
    }
    for (int i = r0 + tid; i < r1; i += 512) __stcg(ub + i, (i < nt) ? an : ap);
    CLUSTER_SYNC();

    // ---- Sinkhorn: 20 x (colpass, rowpass) + final colpass (v) ----
    int Wc = ((rsU >> 3) + 3) & ~3;
    int cbase = cr * Wc;
    for (int it = 0; it < 21; it++) {
        colpass_f(Kb, ub, zb, red, svec, ntp, nc, rsU, Wc, cbase, lane, wid, tid, bn, bp);
        CLUSTER_SYNC();
        if (it == 20) break;
        rowpass_f(Kb, ub, zb, svec, r0, r1, nt, rsU, lane, wid, tid, an, ap);
        CLUSTER_SYNC();
    }

    // ---- finalsum on row slice: sum_i u_i * sum_j K_ij M_ij z_j ----
    // stage v(=z)/255 into smem
    for (int i = tid; i < rsU; i += 512) svec[i] = __ldcg(zb + i) * (1.0f / 255.0f);
    __syncthreads();

    float part = 0.0f;
    for (int i = r0 + wid; i < r1; i += 32) {
        int i2 = i + 16;
        bool has2 = i2 < r1;
        const unsigned char* Kr1 = Kb + (size_t)i * rsU;
        const __half* Mr1 = Mb + (size_t)i * rsU;
        const unsigned char* Kr2 = Kb + (size_t)(has2 ? i2 : i) * rsU;
        const __half* Mr2 = Mb + (size_t)(has2 ? i2 : i) * rsU;
        float a1 = 0.0f, a2 = 0.0f;
#pragma unroll 2
        for (int jj = lane * 4; jj < rsU; jj += 128) {
            float4 zv = *(const float4*)(svec + jj);
            float4 k1 = u8x4_f4(*(const uint32_t*)(Kr1 + jj));
            float4 m1 = h4_f4(*(const uint2*)(Mr1 + jj));
            float4 k2 = u8x4_f4(*(const uint32_t*)(Kr2 + jj));
            float4 m2 = h4_f4(*(const uint2*)(Mr2 + jj));
            a1 = fmaf(k1.x * m1.x, zv.x, a1); a1 = fmaf(k1.y * m1.y, zv.y, a1);
            a1 = fmaf(k1.z * m1.z, zv.z, a1); a1 = fmaf(k1.w * m1.w, zv.w, a1);
            a2 = fmaf(k2.x * m2.x, zv.x, a2); a2 = fmaf(k2.y * m2.y, zv.y, a2);
            a2 = fmaf(k2.z * m2.z, zv.z, a2); a2 = fmaf(k2.w * m2.w, zv.w, a2);
        }
#pragma unroll
        for (int o = 16; o; o >>= 1) {
            a1 += __shfl_down_sync(0xffffffffu, a1, o);
            a2 += __shfl_down_sync(0xffffffffu, a2, o);
        }
        if (lane == 0) {
            part = fmaf(__ldcg(ub + i), a1, part);
            if (has2) part = fmaf(__ldcg(ub + i2), a2, part);
        }
    }
    if (lane == 0) wsum[wid] = part;
    __syncthreads();
    if (tid == 0) {
        float t = 0.0f;
#pragma unroll
        for (int w = 0; w < 16; w++) t += wsum[w];
        d_pfin[bid] = t;
    }
}

// ---------------- 6) final deterministic reduce ------------------------------
__global__ void finalreduce(float* __restrict__ out) {
    __shared__ float rb[256];
    int tid = threadIdx.x;
    rb[tid] = d_pfin[tid];
    __syncthreads();
    for (int st = 128; st; st >>= 1) {
        if (tid < st) rb[tid] += rb[tid + st];
        __syncthreads();
    }
    if (tid == 0) out[0] = 2.0f * rb[0];
}

// ---------------- launch -----------------------------------------------------
extern "C" void kernel_launch(void* const* d_in, const int* in_sizes, int n_in,
                              void* d_out, int out_size) {
    const float* enc = (const float*)d_in[0];
    const int*   t   = (const int*)d_in[2];
    float* out = (float*)d_out;

    part_kernel<<<1, 1024>>>(t);
    gather_kernel<<<dim3(N_TOTAL, S_STEPS), 64>>>(enc);
    gemm_kernel<<<dim3(16, 16, S_STEPS), 256>>>();
    reduce_stats<<<S_STEPS, 256>>>();
    sink_cluster<<<256, 512>>>();
    finalreduce<<<1, 256>>>(out);
}

// round 11
// speedup vs baseline: 1.1064x; 1.1064x over previous
#include <cuda_runtime.h>
#include <cuda_fp16.h>
#include <cuda_bf16.h>
#include <cstdint>

#define N_TOTAL 2048
#define S_STEPS 32
#define DIM 256
#define PER_TS 1507328      // >= rows_max * rsU_max for realistic splits
#define ZSTRIDE 2056

// ---------------- scratch (device globals; no dynamic allocation) ------------
__device__ __align__(16) __half d_Mh[(size_t)S_STEPS * PER_TS];
__device__ __align__(16) __half d_Kh[(size_t)S_STEPS * PER_TS];
__device__ __align__(16) __nv_bfloat16 d_Xhi[(size_t)S_STEPS * N_TOTAL * DIM];
__device__ float d_norm[S_STEPS * N_TOTAL];
__device__ int   d_it[N_TOTAL], d_ic[N_TOTAL];
__device__ int   d_nt, d_nc;
__device__ float d_p;
__device__ float d_lam[S_STEPS], d_delta[S_STEPS];
__device__ __align__(16) float d_u[S_STEPS * ZSTRIDE];
__device__ __align__(16) float d_z[S_STEPS * ZSTRIDE];
__device__ float d_pmax[S_STEPS * 256];
__device__ float d_psum[S_STEPS * 256];
__device__ float d_pfin[128];

// ---------------- fast exp (Cephes, FMA pipe; args in [-8, 0]) ---------------
__device__ __forceinline__ float fexpf_(float x) {
    float z = fmaf(x, 1.4426950408889634f, 12582912.0f);
    float n = z - 12582912.0f;
    float r = fmaf(n, -0.693359375f, x);
    r = fmaf(n, 2.12194440e-4f, r);
    float p = 1.9875691500e-4f;
    p = fmaf(p, r, 1.3981999507e-3f);
    p = fmaf(p, r, 8.3334519073e-3f);
    p = fmaf(p, r, 4.1665795894e-2f);
    p = fmaf(p, r, 1.6666665459e-1f);
    p = fmaf(p, r, 5.0000001201e-1f);
    float e = fmaf(r * r, p, r) + 1.0f;
    int ni = (int)n;
    return __int_as_float(__float_as_int(e) + (ni << 23));
}

__device__ __forceinline__ uint32_t smem_u32(const void* p) {
    uint32_t a;
    asm("{ .reg .u64 t; cvta.to.shared.u64 t, %1; cvt.u32.u64 %0, t; }" : "=r"(a) : "l"(p));
    return a;
}

// 4 halves -> float4
__device__ __forceinline__ float4 h4_f4(uint2 w) {
    float2 a = __half22float2(*reinterpret_cast<__half2*>(&w.x));
    float2 b = __half22float2(*reinterpret_cast<__half2*>(&w.y));
    return make_float4(a.x, a.y, b.x, b.y);
}

#define CLUSTER_SYNC() do { \
    asm volatile("barrier.cluster.arrive.aligned;" ::: "memory"); \
    asm volatile("barrier.cluster.wait.aligned;" ::: "memory"); } while (0)

#define LDSM4(R, addr) \
    asm volatile("ldmatrix.sync.aligned.m8n8.x4.shared.b16 {%0,%1,%2,%3}, [%4];" \
        : "=r"((R)[0]), "=r"((R)[1]), "=r"((R)[2]), "=r"((R)[3]) : "r"(addr))

#define MMA_BF16(C, A, b0_, b1_) \
    asm volatile("mma.sync.aligned.m16n8k16.row.col.f32.bf16.bf16.f32 " \
        "{%0,%1,%2,%3}, {%4,%5,%6,%7}, {%8,%9}, {%0,%1,%2,%3};" \
        : "+f"((C)[0]), "+f"((C)[1]), "+f"((C)[2]), "+f"((C)[3]) \
        : "r"((A)[0]), "r"((A)[1]), "r"((A)[2]), "r"((A)[3]), "r"(b0_), "r"(b1_))

#define CP_ASYNC16(smaddr, gptr, srcsz) \
    asm volatile("cp.async.cg.shared.global [%0], [%1], 16, %2;" \
        :: "r"(smaddr), "l"(gptr), "r"(srcsz))

// ---------------- 1) partition indices (deterministic, single block) ---------
__global__ void part_kernel(const int* __restrict__ t) {
    __shared__ int wcntT[64];
    __shared__ int wprefT[64], wprefC[64];
    int tid = threadIdx.x, lane = tid & 31, wid = tid >> 5;
    for (int c = wid; c < 64; c += 32) {
        int e = c * 32 + lane;
        int f = t[e] > 0;
        unsigned m = __ballot_sync(0xffffffffu, f);
        if (lane == 0) wcntT[c] = __popc(m);
    }
    __syncthreads();
    if (tid == 0) {
        int aT = 0;
        for (int c = 0; c < 64; c++) {
            wprefT[c] = aT;
            wprefC[c] = c * 32 - aT;
            aT += wcntT[c];
        }
        d_nt = aT;
        d_nc = N_TOTAL - aT;
        d_p  = (float)aT / (float)N_TOTAL;
    }
    __syncthreads();
    for (int c = wid; c < 64; c += 32) {
        int e = c * 32 + lane;
        int f = t[e] > 0;
        unsigned m  = __ballot_sync(0xffffffffu, f);
        unsigned lt = ((1u << lane) - 1u);
        if (f) d_it[wprefT[c] + __popc(m & lt)]  = e;
        else   d_ic[wprefC[c] + __popc(~m & lt)] = e;
    }
}

// ---------------- 2) gather rows -> bf16 + fp32 row norms --------------------
// grid (N_TOTAL, S), 64 threads
__global__ void gather_kernel(const float* __restrict__ enc) {
    int r = blockIdx.x, s = blockIdx.y, tid = threadIdx.x;
    int nt = d_nt;
    int src = (r < nt) ? d_it[r] : d_ic[r - nt];
    const float4* in = (const float4*)(enc + ((size_t)src * S_STEPS + s) * DIM);
    float4 v = in[tid];

    __nv_bfloat162 h01 = {__float2bfloat16_rn(v.x), __float2bfloat16_rn(v.y)};
    __nv_bfloat162 h23 = {__float2bfloat16_rn(v.z), __float2bfloat16_rn(v.w)};
    size_t base = ((size_t)s * N_TOTAL + r) * DIM + (size_t)tid * 4;
    uint2 hv = { *(unsigned*)&h01, *(unsigned*)&h23 };
    *(uint2*)(d_Xhi + base) = hv;

    float nrm = v.x * v.x + v.y * v.y + v.z * v.z + v.w * v.w;
    for (int o = 16; o; o >>= 1) nrm += __shfl_down_sync(0xffffffffu, nrm, o);
    __shared__ float sn[2];
    if ((tid & 31) == 0) sn[tid >> 5] = nrm;
    __syncthreads();
    if (tid == 0) d_norm[s * N_TOTAL + r] = sn[0] + sn[1];
}

// ---------------- 3) bf16 GEMM w/ cp.async double buffer ---------------------
// grid (16,16,S), 256 threads (8 warps: 2 m x 4 n), CTA tile 128x128
__global__ void __launch_bounds__(256, 2) gemm_kernel() {
    __shared__ __align__(16) unsigned char sm[41984];
    float* rbuf = (float*)(sm + 40960);

    int tid = threadIdx.x, lane = tid & 31, wid = tid >> 5;
    int wm = wid >> 2, wn = wid & 3;
    int s = blockIdx.z;
    int nt = d_nt, nc = d_nc;
    int i0 = blockIdx.y * 128, j0 = blockIdx.x * 128;
    int pidx = s * 256 + blockIdx.y * 16 + blockIdx.x;

    if (i0 >= nt || j0 >= nc) {
        if (tid == 0) { d_pmax[pidx] = 0.0f; d_psum[pidx] = 0.0f; }
        return;
    }

    uint32_t sb = smem_u32(sm);
    size_t Xbase = (size_t)s * N_TOTAL * DIM;

    int rowA[2], segA[2];
    bool va[2], vb[2];
    const __nv_bfloat16 *gA[2], *gB[2];
#pragma unroll
    for (int h = 0; h < 2; h++) {
        int idx = tid + h * 256;
        rowA[h] = idx >> 2; segA[h] = idx & 3;
        va[h] = (i0 + rowA[h]) < nt;
        vb[h] = (j0 + rowA[h]) < nc;
        int ra = va[h] ? (i0 + rowA[h]) : 0;
        int rb = vb[h] ? (j0 + rowA[h]) : 0;
        gA[h] = d_Xhi + Xbase + (size_t)ra * DIM + segA[h] * 8;
        gB[h] = d_Xhi + Xbase + (size_t)(nt + rb) * DIM + segA[h] * 8;
    }

    float c[4][4][4];
#pragma unroll
    for (int a = 0; a < 4; a++)
#pragma unroll
        for (int b = 0; b < 4; b++)
#pragma unroll
            for (int q = 0; q < 4; q++) c[a][b][q] = 0.0f;

    auto issue = [&](int chunk) {
        int k0 = chunk * 32;
        uint32_t bufo = (uint32_t)(chunk & 1) * 20480u;
#pragma unroll
        for (int h = 0; h < 2; h++) {
            uint32_t doff = (uint32_t)rowA[h] * 80 + (uint32_t)segA[h] * 16;
            CP_ASYNC16(sb + bufo + doff, gA[h] + k0, va[h] ? 16 : 0);
            CP_ASYNC16(sb + bufo + 10240 + doff, gB[h] + k0, vb[h] ? 16 : 0);
        }
        asm volatile("cp.async.commit_group;");
    };

    issue(0);

    for (int chunk = 0; chunk < 8; chunk++) {
        if (chunk < 7) {
            issue(chunk + 1);
            asm volatile("cp.async.wait_group 1;");
        } else {
            asm volatile("cp.async.wait_group 0;");
        }
        __syncthreads();

        uint32_t bufo = (uint32_t)(chunk & 1) * 20480u;
#pragma unroll
        for (int ks = 0; ks < 32; ks += 16) {
            uint32_t colb = (uint32_t)(ks + ((lane >> 4) << 3)) * 2;
            uint32_t ah[4][4], bh2[2][4];
#pragma unroll
            for (int mt = 0; mt < 4; mt++) {
                uint32_t addr = sb + bufo + (uint32_t)(wm * 64 + mt * 16 + (lane & 15)) * 80 + colb;
                LDSM4(ah[mt], addr);
            }
#pragma unroll
            for (int pp = 0; pp < 2; pp++) {
                uint32_t addr = sb + bufo + 10240 + (uint32_t)(wn * 32 + pp * 16 + (lane & 15)) * 80 + colb;
                LDSM4(bh2[pp], addr);
            }
#pragma unroll
            for (int mt = 0; mt < 4; mt++)
#pragma unroll
                for (int nn = 0; nn < 4; nn++) {
                    int pp = nn >> 1, od = nn & 1;
                    MMA_BF16(c[mt][nn], ah[mt], bh2[pp][od], bh2[pp][2 + od]);
                }
        }
        __syncthreads();
    }

    float* nbs = (float*)sm;
    for (int q = tid; q < 128; q += 256)
        nbs[q] = (j0 + q < nc) ? d_norm[s * N_TOTAL + nt + j0 + q] : 0.0f;
    __syncthreads();

    int rsU = (nc + 16) & ~15;
    float lmax = 0.0f, lsum = 0.0f;
#pragma unroll
    for (int mt = 0; mt < 4; mt++) {
        int gi0 = i0 + wm * 64 + mt * 16 + (lane >> 2);
        int gi1 = gi0 + 8;
        float na0 = (gi0 < nt) ? d_norm[s * N_TOTAL + gi0] : 0.0f;
        float na1 = (gi1 < nt) ? d_norm[s * N_TOTAL + gi1] : 0.0f;
#pragma unroll
        for (int nn = 0; nn < 4; nn++) {
            int lj = wn * 32 + nn * 8 + (lane & 3) * 2;
            int gj = j0 + lj;
            float nb0 = nbs[lj], nb1 = nbs[lj + 1];
            bool vj0 = gj < nc, vj1 = (gj + 1) < nc;
            float m00 = na0 + nb0 - 2.0f * c[mt][nn][0];
            float m01 = na0 + nb1 - 2.0f * c[mt][nn][1];
            float m10 = na1 + nb0 - 2.0f * c[mt][nn][2];
            float m11 = na1 + nb1 - 2.0f * c[mt][nn][3];
            if (gi0 < nt) {
                __half* Mr = d_Mh + (size_t)s * PER_TS + (size_t)gi0 * rsU + gj;
                if (vj0) { lmax = fmaxf(lmax, m00); lsum += m00; }
                if (vj1) { lmax = fmaxf(lmax, m01); lsum += m01; }
                if (vj0 && vj1) *(__half2*)Mr = __floats2half2_rn(m00, m01);
                else if (vj0)   *Mr = __float2half_rn(m00);
            }
            if (gi1 < nt) {
                __half* Mr = d_Mh + (size_t)s * PER_TS + (size_t)gi1 * rsU + gj;
                if (vj0) { lmax = fmaxf(lmax, m10); lsum += m10; }
                if (vj1) { lmax = fmaxf(lmax, m11); lsum += m11; }
                if (vj0 && vj1) *(__half2*)Mr = __floats2half2_rn(m10, m11);
                else if (vj0)   *Mr = __float2half_rn(m10);
            }
        }
    }

    rbuf[tid] = lmax; __syncthreads();
    for (int st = 128; st; st >>= 1) {
        if (tid < st) rbuf[tid] = fmaxf(rbuf[tid], rbuf[tid + st]);
        __syncthreads();
    }
    if (tid == 0) d_pmax[pidx] = rbuf[0];
    __syncthreads();
    rbuf[tid] = lsum; __syncthreads();
    for (int st = 128; st; st >>= 1) {
        if (tid < st) rbuf[tid] += rbuf[tid + st];
        __syncthreads();
    }
    if (tid == 0) d_psum[pidx] = rbuf[0];
}

// ---------------- 4) per-timestep stats --------------------------------------
__global__ void reduce_stats() {
    __shared__ float rb[256];
    int s = blockIdx.x, tid = threadIdx.x;
    float mv = d_pmax[s * 256 + tid];
    float sv = d_psum[s * 256 + tid];
    rb[tid] = mv; __syncthreads();
    for (int st = 128; st; st >>= 1) {
        if (tid < st) rb[tid] = fmaxf(rb[tid], rb[tid + st]);
        __syncthreads();
    }
    float mx = rb[0];
    __syncthreads();
    rb[tid] = sv; __syncthreads();
    for (int st = 128; st; st >>= 1) {
        if (tid < st) rb[tid] += rb[tid + st];
        __syncthreads();
    }
    if (tid == 0) {
        d_delta[s] = mx;
        d_lam[s] = ((float)d_nt * (float)d_nc) / rb[0];
    }
}

// ---------------- 5) persistent Sinkhorn: 32 clusters of 4 CTAs, 1024 thr ----
// 128 CTAs total -> at most 1 CTA per SM (no co-residency imbalance).
__device__ __forceinline__ void colpass_f(
    const __half* Kb, const float* ub, float* zb, float (*red)[308], float* svec,
    int ntp, int nc, int rsU, int Wc, int cbase, int lane, int wid, int tid,
    float bn, float bp)
{
    // stage u into smem (one L2 pass)
    for (int i = tid; i < ntp; i += 1024) svec[i] = __ldcg(ub + i);
    __syncthreads();

    float acc[3][4] = {{0.f,0.f,0.f,0.f},{0.f,0.f,0.f,0.f},{0.f,0.f,0.f,0.f}};
    int l4 = lane * 4;
    int jj[3]; bool v[3];
#pragma unroll
    for (int c3 = 0; c3 < 3; c3++) {
        jj[c3] = cbase + l4 + c3 * 128;
        v[c3] = (l4 + c3 * 128 < Wc) && (jj[c3] < rsU);
    }
#pragma unroll 4
    for (int i = wid; i < ntp; i += 32) {
        float u = svec[i];
        const __half* Kr = Kb + (size_t)i * rsU;
#pragma unroll
        for (int c3 = 0; c3 < 3; c3++) {
            if (v[c3]) {
                float4 f = h4_f4(*(const uint2*)(Kr + jj[c3]));
                acc[c3][0] = fmaf(f.x, u, acc[c3][0]);
                acc[c3][1] = fmaf(f.y, u, acc[c3][1]);
                acc[c3][2] = fmaf(f.z, u, acc[c3][2]);
                acc[c3][3] = fmaf(f.w, u, acc[c3][3]);
            }
        }
    }
#pragma unroll
    for (int c3 = 0; c3 < 3; c3++) {
        if (v[c3]) {
#pragma unroll
            for (int q = 0; q < 4; q++) red[wid][c3 * 128 + l4 + q] = acc[c3][q];
        }
    }
    __syncthreads();
    for (int cc = tid; cc < Wc; cc += 1024) {
        int j = cbase + cc;
        if (j >= rsU) continue;
        float t = red[0][cc];
#pragma unroll
        for (int w = 1; w < 32; w++) t += red[w][cc];
        float zv = (j < nc) ? (bn / t) : ((j == nc) ? (bp / t) : 0.0f);
        __stcg(zb + j, zv);
    }
    __syncthreads();
}

__device__ __forceinline__ void rowpass_f(
    const __half* Kb, float* ub, const float* zb, float* svec,
    int r0, int r1, int nt, int rsU, int lane, int wid, int tid, float an, float ap)
{
    // stage z into smem (one L2 pass)
    for (int i = tid; i < rsU; i += 1024) svec[i] = __ldcg(zb + i);
    __syncthreads();

    for (int i = r0 + wid; i < r1; i += 64) {
        int i2 = i + 32;
        bool has2 = i2 < r1;
        const __half* Kr1 = Kb + (size_t)i * rsU;
        const __half* Kr2 = Kb + (size_t)(has2 ? i2 : i) * rsU;
        float a1 = 0.0f, a2 = 0.0f;
#pragma unroll 4
        for (int jj = lane * 4; jj < rsU; jj += 128) {
            float4 zv = *(const float4*)(svec + jj);
            float4 k1 = h4_f4(*(const uint2*)(Kr1 + jj));
            float4 k2 = h4_f4(*(const uint2*)(Kr2 + jj));
            a1 = fmaf(k1.x, zv.x, a1); a1 = fmaf(k1.y, zv.y, a1);
            a1 = fmaf(k1.z, zv.z, a1); a1 = fmaf(k1.w, zv.w, a1);
            a2 = fmaf(k2.x, zv.x, a2); a2 = fmaf(k2.y, zv.y, a2);
            a2 = fmaf(k2.z, zv.z, a2); a2 = fmaf(k2.w, zv.w, a2);
        }
#pragma unroll
        for (int o = 16; o; o >>= 1) {
            a1 += __shfl_down_sync(0xffffffffu, a1, o);
            a2 += __shfl_down_sync(0xffffffffu, a2, o);
        }
        if (lane == 0) {
            __stcg(ub + i, ((i < nt) ? an : ap) / a1);
            if (has2) __stcg(ub + i2, ((i2 < nt) ? an : ap) / a2);
        }
    }
    __syncthreads();
}

__global__ void __cluster_dims__(4, 1, 1) __launch_bounds__(1024, 1) sink_cluster() {
    __shared__ float red[32][308];
    __shared__ float wsum[32];
    __shared__ __align__(16) float svec[2064];
    int bid = blockIdx.x;
    int s = bid >> 2, cr = bid & 3;
    int tid = threadIdx.x, lane = tid & 31, wid = tid >> 5;
    int nt = d_nt, nc = d_nc, ntp = nt + 1;
    int rsU = (nc + 16) & ~15;
    float lam = d_lam[s], delta = d_delta[s], p = d_p;
    float an = p / (float)nt, ap = 1.0f - p;
    float bn = (1.0f - p) / (float)nc, bp = p;
    __half* Mb = d_Mh + (size_t)s * PER_TS;
    __half* Kb = d_Kh + (size_t)s * PER_TS;
    float* ub = d_u + s * ZSTRIDE;
    float* zb = d_z + s * ZSTRIDE;

    // ---- Phase A: build K fp16 + M pads on row slice; init u slice ----
    int H = (ntp + 3) >> 2;
    int r0 = cr * H;
    int r1 = min(ntp, r0 + H);
    float kpad = fexpf_(-lam * delta) + 1e-6f;
    float kcorner = 1.0f + 1e-6f;
    for (int r = r0; r < r1; r++) {
        __half* Mw = Mb + (size_t)r * rsU;
        __half* Kr = Kb + (size_t)r * rsU;
        for (int c = tid * 2; c < rsU; c += 2048) {
            float kk[2];
#pragma unroll
            for (int q = 0; q < 2; q++) {
                int cc = c + q;
                float kv;
                if (r < nt) {
                    if (cc < nc) {
                        kv = fexpf_(-lam * __half2float(Mw[cc])) + 1e-6f;
                    } else if (cc == nc) {
                        kv = kpad; Mw[cc] = __float2half_rn(delta);
                    } else {
                        kv = 0.0f; Mw[cc] = __float2half_rn(0.0f);
                    }
                } else {
                    if (cc < nc) { kv = kpad; Mw[cc] = __float2half_rn(delta); }
                    else if (cc == nc) { kv = kcorner; Mw[cc] = __float2half_rn(0.0f); }
                    else { kv = 0.0f; Mw[cc] = __float2half_rn(0.0f); }
                }
                kk[q] = kv;
            }
            __half2 h2 = __floats2half2_rn(kk[0], kk[1]);
            *(unsigned*)(Kr + c) = *(unsigned*)&h2;
        }
    }
    for (int i = r0 + tid; i < r1; i += 1024) __stcg(ub + i, (i < nt) ? an : ap);
    CLUSTER_SYNC();

    // ---- Sinkhorn: 20 x (colpass, rowpass) + final colpass (v) ----
    int Wc = ((rsU >> 2) + 3) & ~3;
    int cbase = cr * Wc;
    for (int it = 0; it < 21; it++) {
        colpass_f(Kb, ub, zb, red, svec, ntp, nc, rsU, Wc, cbase, lane, wid, tid, bn, bp);
        CLUSTER_SYNC();
        if (it == 20) break;
        rowpass_f(Kb, ub, zb, svec, r0, r1, nt, rsU, lane, wid, tid, an, ap);
        CLUSTER_SYNC();
    }

    // ---- finalsum on row slice: sum_i u_i * sum_j K_ij M_ij z_j ----
    // stage v(=z) into smem
    for (int i = tid; i < rsU; i += 1024) svec[i] = __ldcg(zb + i);
    __syncthreads();

    float part = 0.0f;
    for (int i = r0 + wid; i < r1; i += 64) {
        int i2 = i + 32;
        bool has2 = i2 < r1;
        const __half* Kr1 = Kb + (size_t)i * rsU;
        const __half* Mr1 = Mb + (size_t)i * rsU;
        const __half* Kr2 = Kb + (size_t)(has2 ? i2 : i) * rsU;
        const __half* Mr2 = Mb + (size_t)(has2 ? i2 : i) * rsU;
        float a1 = 0.0f, a2 = 0.0f;
#pragma unroll 2
        for (int jj = lane * 4; jj < rsU; jj += 128) {
            float4 zv = *(const float4*)(svec + jj);
            float4 k1 = h4_f4(*(const uint2*)(Kr1 + jj));
            float4 m1 = h4_f4(*(const uint2*)(Mr1 + jj));
            float4 k2 = h4_f4(*(const uint2*)(Kr2 + jj));
            float4 m2 = h4_f4(*(const uint2*)(Mr2 + jj));
            a1 = fmaf(k1.x * m1.x, zv.x, a1); a1 = fmaf(k1.y * m1.y, zv.y, a1);
            a1 = fmaf(k1.z * m1.z, zv.z, a1); a1 = fmaf(k1.w * m1.w, zv.w, a1);
            a2 = fmaf(k2.x * m2.x, zv.x, a2); a2 = fmaf(k2.y * m2.y, zv.y, a2);
            a2 = fmaf(k2.z * m2.z, zv.z, a2); a2 = fmaf(k2.w * m2.w, zv.w, a2);
        }
#pragma unroll
        for (int o = 16; o; o >>= 1) {
            a1 += __shfl_down_sync(0xffffffffu, a1, o);
            a2 += __shfl_down_sync(0xffffffffu, a2, o);
        }
        if (lane == 0) {
            part = fmaf(__ldcg(ub + i), a1, part);
            if (has2) part = fmaf(__ldcg(ub + i2), a2, part);
        }
    }
    if (lane == 0) wsum[wid] = part;
    __syncthreads();
    if (tid == 0) {
        float t = 0.0f;
#pragma unroll
        for (int w = 0; w < 32; w++) t += wsum[w];
        d_pfin[bid] = t;
    }
}

// ---------------- 6) final deterministic reduce ------------------------------
__global__ void finalreduce(float* __restrict__ out) {
    __shared__ float rb[128];
    int tid = threadIdx.x;
    rb[tid] = d_pfin[tid];
    __syncthreads();
    for (int st = 64; st; st >>= 1) {
        if (tid < st) rb[tid] += rb[tid + st];
        __syncthreads();
    }
    if (tid == 0) out[0] = 2.0f * rb[0];
}

// ---------------- launch -----------------------------------------------------
extern "C" void kernel_launch(void* const* d_in, const int* in_sizes, int n_in,
                              void* d_out, int out_size) {
    const float* enc = (const float*)d_in[0];
    const int*   t   = (const int*)d_in[2];
    float* out = (float*)d_out;

    part_kernel<<<1, 1024>>>(t);
    gather_kernel<<<dim3(N_TOTAL, S_STEPS), 64>>>(enc);
    gemm_kernel<<<dim3(16, 16, S_STEPS), 256>>>();
    reduce_stats<<<S_STEPS, 256>>>();
    sink_cluster<<<128, 1024>>>();
    finalreduce<<<1, 128>>>(out);
}

// round 12
// speedup vs baseline: 1.1797x; 1.0662x over previous
#include <cuda_runtime.h>
#include <cuda_fp16.h>
#include <cuda_bf16.h>
#include <cstdint>

#define N_TOTAL 2048
#define S_STEPS 32
#define DIM 256
#define PER_TS 1507328      // >= rows_max * rsU_max (rsU now <= 1152)
#define ZSTRIDE 2056
#define NCHMAX 9            // max column chunks of 128 (rsU <= 1152)

// ---------------- scratch (device globals; no dynamic allocation) ------------
__device__ __align__(16) __half d_Mh[(size_t)S_STEPS * PER_TS];
__device__ __align__(16) __half d_Kh[(size_t)S_STEPS * PER_TS];
__device__ __align__(16) __nv_bfloat16 d_Xhi[(size_t)S_STEPS * N_TOTAL * DIM];
__device__ float d_norm[S_STEPS * N_TOTAL];
__device__ int   d_it[N_TOTAL], d_ic[N_TOTAL];
__device__ int   d_nt, d_nc;
__device__ float d_p;
__device__ float d_lam[S_STEPS], d_delta[S_STEPS];
__device__ __align__(16) float d_u[S_STEPS * ZSTRIDE];
__device__ __align__(16) float d_cpart[(size_t)S_STEPS * 8 * 1152];
__device__ float d_pmax[S_STEPS * 256];
__device__ float d_psum[S_STEPS * 256];
__device__ float d_pfin[256];

// ---------------- fast exp (Cephes, FMA pipe; args in [-8, 0]) ---------------
__device__ __forceinline__ float fexpf_(float x) {
    float z = fmaf(x, 1.4426950408889634f, 12582912.0f);
    float n = z - 12582912.0f;
    float r = fmaf(n, -0.693359375f, x);
    r = fmaf(n, 2.12194440e-4f, r);
    float p = 1.9875691500e-4f;
    p = fmaf(p, r, 1.3981999507e-3f);
    p = fmaf(p, r, 8.3334519073e-3f);
    p = fmaf(p, r, 4.1665795894e-2f);
    p = fmaf(p, r, 1.6666665459e-1f);
    p = fmaf(p, r, 5.0000001201e-1f);
    float e = fmaf(r * r, p, r) + 1.0f;
    int ni = (int)n;
    return __int_as_float(__float_as_int(e) + (ni << 23));
}

__device__ __forceinline__ uint32_t smem_u32(const void* p) {
    uint32_t a;
    asm("{ .reg .u64 t; cvta.to.shared.u64 t, %1; cvt.u32.u64 %0, t; }" : "=r"(a) : "l"(p));
    return a;
}

// 4 halves -> float4
__device__ __forceinline__ float4 h4_f4(uint2 w) {
    float2 a = __half22float2(*reinterpret_cast<__half2*>(&w.x));
    float2 b = __half22float2(*reinterpret_cast<__half2*>(&w.y));
    return make_float4(a.x, a.y, b.x, b.y);
}

#define CLUSTER_SYNC() do { \
    asm volatile("barrier.cluster.arrive.aligned;" ::: "memory"); \
    asm volatile("barrier.cluster.wait.aligned;" ::: "memory"); } while (0)

#define LDSM4(R, addr) \
    asm volatile("ldmatrix.sync.aligned.m8n8.x4.shared.b16 {%0,%1,%2,%3}, [%4];" \
        : "=r"((R)[0]), "=r"((R)[1]), "=r"((R)[2]), "=r"((R)[3]) : "r"(addr))

#define MMA_BF16(C, A, b0_, b1_) \
    asm volatile("mma.sync.aligned.m16n8k16.row.col.f32.bf16.bf16.f32 " \
        "{%0,%1,%2,%3}, {%4,%5,%6,%7}, {%8,%9}, {%0,%1,%2,%3};" \
        : "+f"((C)[0]), "+f"((C)[1]), "+f"((C)[2]), "+f"((C)[3]) \
        : "r"((A)[0]), "r"((A)[1]), "r"((A)[2]), "r"((A)[3]), "r"(b0_), "r"(b1_))

#define CP_ASYNC16(smaddr, gptr, srcsz) \
    asm volatile("cp.async.cg.shared.global [%0], [%1], 16, %2;" \
        :: "r"(smaddr), "l"(gptr), "r"(srcsz))

// ---------------- 1) partition indices (deterministic, single block) ---------
__global__ void part_kernel(const int* __restrict__ t) {
    __shared__ int wcntT[64];
    __shared__ int wprefT[64], wprefC[64];
    int tid = threadIdx.x, lane = tid & 31, wid = tid >> 5;
    for (int c = wid; c < 64; c += 32) {
        int e = c * 32 + lane;
        int f = t[e] > 0;
        unsigned m = __ballot_sync(0xffffffffu, f);
        if (lane == 0) wcntT[c] = __popc(m);
    }
    __syncthreads();
    if (tid == 0) {
        int aT = 0;
        for (int c = 0; c < 64; c++) {
            wprefT[c] = aT;
            wprefC[c] = c * 32 - aT;
            aT += wcntT[c];
        }
        d_nt = aT;
        d_nc = N_TOTAL - aT;
        d_p  = (float)aT / (float)N_TOTAL;
    }
    __syncthreads();
    for (int c = wid; c < 64; c += 32) {
        int e = c * 32 + lane;
        int f = t[e] > 0;
        unsigned m  = __ballot_sync(0xffffffffu, f);
        unsigned lt = ((1u << lane) - 1u);
        if (f) d_it[wprefT[c] + __popc(m & lt)]  = e;
        else   d_ic[wprefC[c] + __popc(~m & lt)] = e;
    }
}

// ---------------- 2) gather rows -> bf16 + fp32 row norms --------------------
// grid (N_TOTAL, S), 64 threads
__global__ void gather_kernel(const float* __restrict__ enc) {
    int r = blockIdx.x, s = blockIdx.y, tid = threadIdx.x;
    int nt = d_nt;
    int src = (r < nt) ? d_it[r] : d_ic[r - nt];
    const float4* in = (const float4*)(enc + ((size_t)src * S_STEPS + s) * DIM);
    float4 v = in[tid];

    __nv_bfloat162 h01 = {__float2bfloat16_rn(v.x), __float2bfloat16_rn(v.y)};
    __nv_bfloat162 h23 = {__float2bfloat16_rn(v.z), __float2bfloat16_rn(v.w)};
    size_t base = ((size_t)s * N_TOTAL + r) * DIM + (size_t)tid * 4;
    uint2 hv = { *(unsigned*)&h01, *(unsigned*)&h23 };
    *(uint2*)(d_Xhi + base) = hv;

    float nrm = v.x * v.x + v.y * v.y + v.z * v.z + v.w * v.w;
    for (int o = 16; o; o >>= 1) nrm += __shfl_down_sync(0xffffffffu, nrm, o);
    __shared__ float sn[2];
    if ((tid & 31) == 0) sn[tid >> 5] = nrm;
    __syncthreads();
    if (tid == 0) d_norm[s * N_TOTAL + r] = sn[0] + sn[1];
}

// ---------------- 3) bf16 GEMM w/ cp.async double buffer ---------------------
// grid (16,16,S), 256 threads (8 warps: 2 m x 4 n), CTA tile 128x128
__global__ void __launch_bounds__(256, 2) gemm_kernel() {
    __shared__ __align__(16) unsigned char sm[41984];
    float* rbuf = (float*)(sm + 40960);

    int tid = threadIdx.x, lane = tid & 31, wid = tid >> 5;
    int wm = wid >> 2, wn = wid & 3;
    int s = blockIdx.z;
    int nt = d_nt, nc = d_nc;
    int i0 = blockIdx.y * 128, j0 = blockIdx.x * 128;
    int pidx = s * 256 + blockIdx.y * 16 + blockIdx.x;

    if (i0 >= nt || j0 >= nc) {
        if (tid == 0) { d_pmax[pidx] = 0.0f; d_psum[pidx] = 0.0f; }
        return;
    }

    uint32_t sb = smem_u32(sm);
    size_t Xbase = (size_t)s * N_TOTAL * DIM;

    int rowA[2], segA[2];
    bool va[2], vb[2];
    const __nv_bfloat16 *gA[2], *gB[2];
#pragma unroll
    for (int h = 0; h < 2; h++) {
        int idx = tid + h * 256;
        rowA[h] = idx >> 2; segA[h] = idx & 3;
        va[h] = (i0 + rowA[h]) < nt;
        vb[h] = (j0 + rowA[h]) < nc;
        int ra = va[h] ? (i0 + rowA[h]) : 0;
        int rb = vb[h] ? (j0 + rowA[h]) : 0;
        gA[h] = d_Xhi + Xbase + (size_t)ra * DIM + segA[h] * 8;
        gB[h] = d_Xhi + Xbase + (size_t)(nt + rb) * DIM + segA[h] * 8;
    }

    float c[4][4][4];
#pragma unroll
    for (int a = 0; a < 4; a++)
#pragma unroll
        for (int b = 0; b < 4; b++)
#pragma unroll
            for (int q = 0; q < 4; q++) c[a][b][q] = 0.0f;

    auto issue = [&](int chunk) {
        int k0 = chunk * 32;
        uint32_t bufo = (uint32_t)(chunk & 1) * 20480u;
#pragma unroll
        for (int h = 0; h < 2; h++) {
            uint32_t doff = (uint32_t)rowA[h] * 80 + (uint32_t)segA[h] * 16;
            CP_ASYNC16(sb + bufo + doff, gA[h] + k0, va[h] ? 16 : 0);
            CP_ASYNC16(sb + bufo + 10240 + doff, gB[h] + k0, vb[h] ? 16 : 0);
        }
        asm volatile("cp.async.commit_group;");
    };

    issue(0);

    for (int chunk = 0; chunk < 8; chunk++) {
        if (chunk < 7) {
            issue(chunk + 1);
            asm volatile("cp.async.wait_group 1;");
        } else {
            asm volatile("cp.async.wait_group 0;");
        }
        __syncthreads();

        uint32_t bufo = (uint32_t)(chunk & 1) * 20480u;
#pragma unroll
        for (int ks = 0; ks < 32; ks += 16) {
            uint32_t colb = (uint32_t)(ks + ((lane >> 4) << 3)) * 2;
            uint32_t ah[4][4], bh2[2][4];
#pragma unroll
            for (int mt = 0; mt < 4; mt++) {
                uint32_t addr = sb + bufo + (uint32_t)(wm * 64 + mt * 16 + (lane & 15)) * 80 + colb;
                LDSM4(ah[mt], addr);
            }
#pragma unroll
            for (int pp = 0; pp < 2; pp++) {
                uint32_t addr = sb + bufo + 10240 + (uint32_t)(wn * 32 + pp * 16 + (lane & 15)) * 80 + colb;
                LDSM4(bh2[pp], addr);
            }
#pragma unroll
            for (int mt = 0; mt < 4; mt++)
#pragma unroll
                for (int nn = 0; nn < 4; nn++) {
                    int pp = nn >> 1, od = nn & 1;
                    MMA_BF16(c[mt][nn], ah[mt], bh2[pp][od], bh2[pp][2 + od]);
                }
        }
        __syncthreads();
    }

    float* nbs = (float*)sm;
    for (int q = tid; q < 128; q += 256)
        nbs[q] = (j0 + q < nc) ? d_norm[s * N_TOTAL + nt + j0 + q] : 0.0f;
    __syncthreads();

    int rsU = (nc + 128) & ~127;
    float lmax = 0.0f, lsum = 0.0f;
#pragma unroll
    for (int mt = 0; mt < 4; mt++) {
        int gi0 = i0 + wm * 64 + mt * 16 + (lane >> 2);
        int gi1 = gi0 + 8;
        float na0 = (gi0 < nt) ? d_norm[s * N_TOTAL + gi0] : 0.0f;
        float na1 = (gi1 < nt) ? d_norm[s * N_TOTAL + gi1] : 0.0f;
#pragma unroll
        for (int nn = 0; nn < 4; nn++) {
            int lj = wn * 32 + nn * 8 + (lane & 3) * 2;
            int gj = j0 + lj;
            float nb0 = nbs[lj], nb1 = nbs[lj + 1];
            bool vj0 = gj < nc, vj1 = (gj + 1) < nc;
            float m00 = na0 + nb0 - 2.0f * c[mt][nn][0];
            float m01 = na0 + nb1 - 2.0f * c[mt][nn][1];
            float m10 = na1 + nb0 - 2.0f * c[mt][nn][2];
            float m11 = na1 + nb1 - 2.0f * c[mt][nn][3];
            if (gi0 < nt) {
                __half* Mr = d_Mh + (size_t)s * PER_TS + (size_t)gi0 * rsU + gj;
                if (vj0) { lmax = fmaxf(lmax, m00); lsum += m00; }
                if (vj1) { lmax = fmaxf(lmax, m01); lsum += m01; }
                if (vj0 && vj1) *(__half2*)Mr = __floats2half2_rn(m00, m01);
                else if (vj0)   *Mr = __float2half_rn(m00);
            }
            if (gi1 < nt) {
                __half* Mr = d_Mh + (size_t)s * PER_TS + (size_t)gi1 * rsU + gj;
                if (vj0) { lmax = fmaxf(lmax, m10); lsum += m10; }
                if (vj1) { lmax = fmaxf(lmax, m11); lsum += m11; }
                if (vj0 && vj1) *(__half2*)Mr = __floats2half2_rn(m10, m11);
                else if (vj0)   *Mr = __float2half_rn(m10);
            }
        }
    }

    rbuf[tid] = lmax; __syncthreads();
    for (int st = 128; st; st >>= 1) {
        if (tid < st) rbuf[tid] = fmaxf(rbuf[tid], rbuf[tid + st]);
        __syncthreads();
    }
    if (tid == 0) d_pmax[pidx] = rbuf[0];
    __syncthreads();
    rbuf[tid] = lsum; __syncthreads();
    for (int st = 128; st; st >>= 1) {
        if (tid < st) rbuf[tid] += rbuf[tid + st];
        __syncthreads();
    }
    if (tid == 0) d_psum[pidx] = rbuf[0];
}

// ---------------- 4) per-timestep stats --------------------------------------
__global__ void reduce_stats() {
    __shared__ float rb[256];
    int s = blockIdx.x, tid = threadIdx.x;
    float mv = d_pmax[s * 256 + tid];
    float sv = d_psum[s * 256 + tid];
    rb[tid] = mv; __syncthreads();
    for (int st = 128; st; st >>= 1) {
        if (tid < st) rb[tid] = fmaxf(rb[tid], rb[tid + st]);
        __syncthreads();
    }
    float mx = rb[0];
    __syncthreads();
    rb[tid] = sv; __syncthreads();
    for (int st = 128; st; st >>= 1) {
        if (tid < st) rb[tid] += rb[tid + st];
        __syncthreads();
    }
    if (tid == 0) {
        d_delta[s] = mx;
        d_lam[s] = ((float)d_nt * (float)d_nc) / rb[0];
    }
}

// ---------------- 5) persistent fused Sinkhorn: 32 clusters x 8 CTAs x 256 ----
// One K-pass per iteration: u-update + column partials fused; z rebuilt
// locally in smem from the 8 CTA partials after ONE cluster sync.
__global__ void __cluster_dims__(8, 1, 1) __launch_bounds__(256, 2) sink_cluster() {
    __shared__ float redf[8 * 1160];
    __shared__ float wsum[8];
    __shared__ __align__(16) float svec[1156];
    int bid = blockIdx.x;
    int s = bid >> 3, cr = bid & 7;
    int tid = threadIdx.x, lane = tid & 31, wid = tid >> 5; // 8 warps
    int nt = d_nt, nc = d_nc, ntp = nt + 1;
    int rsU = (nc + 128) & ~127;
    int nch = rsU >> 7;
    float lam = d_lam[s], delta = d_delta[s], p = d_p;
    float an = p / (float)nt, ap = 1.0f - p;
    float bn = (1.0f - p) / (float)nc, bp = p;
    __half* Mb = d_Mh + (size_t)s * PER_TS;
    __half* Kb = d_Kh + (size_t)s * PER_TS;
    float* ub = d_u + s * ZSTRIDE;
    float* cp = d_cpart + (size_t)s * 8 * 1152;

    // ---- Phase A: build K fp16 + M pads on private row strip ----
    int H = (ntp + 7) >> 3;
    int r0 = cr * H;
    int r1 = min(ntp, r0 + H);
    float kpad = fexpf_(-lam * delta) + 1e-6f;
    float kcorner = 1.0f + 1e-6f;
    for (int r = r0; r < r1; r++) {
        __half* Mw = Mb + (size_t)r * rsU;
        __half* Kr = Kb + (size_t)r * rsU;
        for (int c = tid * 2; c < rsU; c += 512) {
            float kk[2];
#pragma unroll
            for (int q = 0; q < 2; q++) {
                int cc = c + q;
                float kv;
                if (r < nt) {
                    if (cc < nc) {
                        kv = fexpf_(-lam * __half2float(Mw[cc])) + 1e-6f;
                    } else if (cc == nc) {
                        kv = kpad; Mw[cc] = __float2half_rn(delta);
                    } else {
                        kv = 0.0f; Mw[cc] = __float2half_rn(0.0f);
                    }
                } else {
                    if (cc < nc) { kv = kpad; Mw[cc] = __float2half_rn(delta); }
                    else if (cc == nc) { kv = kcorner; Mw[cc] = __float2half_rn(0.0f); }
                    else { kv = 0.0f; Mw[cc] = __float2half_rn(0.0f); }
                }
                kk[q] = kv;
            }
            __half2 h2 = __floats2half2_rn(kk[0], kk[1]);
            *(unsigned*)(Kr + c) = *(unsigned*)&h2;
        }
    }
    __syncthreads();   // K strip is CTA-private; no cluster sync needed

    // ---- fused pass: mode 0 = u is 'a' (init colsum); mode 1 = full step ----
    auto fused_pass = [&](int mode) {
        float acc[NCHMAX][4];
#pragma unroll
        for (int c = 0; c < NCHMAX; c++) {
            acc[c][0] = 0.f; acc[c][1] = 0.f; acc[c][2] = 0.f; acc[c][3] = 0.f;
        }
        for (int i = r0 + wid; i < r1; i += 8) {
            const __half* Kr = Kb + (size_t)i * rsU;
            float4 kf[NCHMAX];
            float d = 0.0f;
#pragma unroll
            for (int c = 0; c < NCHMAX; c++) {
                if (c < nch) {
                    int jj = c * 128 + lane * 4;
                    uint2 w = *(const uint2*)(Kr + jj);
                    kf[c] = h4_f4(w);
                    if (mode) {
                        float4 zv = *(const float4*)(svec + jj);
                        d = fmaf(kf[c].x, zv.x, d);
                        d = fmaf(kf[c].y, zv.y, d);
                        d = fmaf(kf[c].z, zv.z, d);
                        d = fmaf(kf[c].w, zv.w, d);
                    }
                }
            }
            float ui;
            if (mode) {
#pragma unroll
                for (int o = 16; o; o >>= 1) d += __shfl_down_sync(0xffffffffu, d, o);
                d = __shfl_sync(0xffffffffu, d, 0);
                ui = ((i < nt) ? an : ap) / d;
                if (lane == 0) __stcg(ub + i, ui);
            } else {
                ui = (i < nt) ? an : ap;
            }
#pragma unroll
            for (int c = 0; c < NCHMAX; c++) {
                if (c < nch) {
                    acc[c][0] = fmaf(ui, kf[c].x, acc[c][0]);
                    acc[c][1] = fmaf(ui, kf[c].y, acc[c][1]);
                    acc[c][2] = fmaf(ui, kf[c].z, acc[c][2]);
                    acc[c][3] = fmaf(ui, kf[c].w, acc[c][3]);
                }
            }
        }
        // merge 8 warp-private partials -> CTA partial -> global cpart
#pragma unroll
        for (int c = 0; c < NCHMAX; c++) {
            if (c < nch)
                *(float4*)&redf[wid * 1160 + c * 128 + lane * 4] = *(float4*)acc[c];
        }
        __syncthreads();
        for (int j = tid; j < rsU; j += 256) {
            float t = redf[j];
#pragma unroll
            for (int w = 1; w < 8; w++) t += redf[w * 1160 + j];
            __stcg(cp + (size_t)cr * 1152 + j, t);
        }
    };

    // rebuild full z locally in smem from the 8 CTA partials
    auto build_z = [&]() {
        for (int j = tid; j < rsU; j += 256) {
            float t = 0.0f;
#pragma unroll
            for (int c2 = 0; c2 < 8; c2++) t += __ldcg(cp + (size_t)c2 * 1152 + j);
            svec[j] = (j < nc) ? (bn / t) : ((j == nc) ? (bp / t) : 0.0f);
        }
        __syncthreads();
    };

    // pass 0: colsum with u = a
    fused_pass(0);
    CLUSTER_SYNC();
    build_z();

    // 20 fused iterations; after the 20th, svec holds v = b/(K^T u_final)
    for (int it = 0; it < 20; it++) {
        fused_pass(1);
        CLUSTER_SYNC();
        build_z();
    }

    // ---- finalsum on row strip: sum_i u_i * sum_j K_ij M_ij v_j ----
    float part = 0.0f;
    for (int i = r0 + wid; i < r1; i += 8) {
        const __half* Kr = Kb + (size_t)i * rsU;
        const __half* Mr = Mb + (size_t)i * rsU;
        float a1 = 0.0f;
#pragma unroll
        for (int c = 0; c < NCHMAX; c++) {
            if (c < nch) {
                int jj = c * 128 + lane * 4;
                float4 kf = h4_f4(*(const uint2*)(Kr + jj));
                float4 mf = h4_f4(*(const uint2*)(Mr + jj));
                float4 zv = *(const float4*)(svec + jj);
                a1 = fmaf(kf.x * mf.x, zv.x, a1);
                a1 = fmaf(kf.y * mf.y, zv.y, a1);
                a1 = fmaf(kf.z * mf.z, zv.z, a1);
                a1 = fmaf(kf.w * mf.w, zv.w, a1);
            }
        }
#pragma unroll
        for (int o = 16; o; o >>= 1) a1 += __shfl_down_sync(0xffffffffu, a1, o);
        if (lane == 0) part = fmaf(__ldcg(ub + i), a1, part);
    }
    if (lane == 0) wsum[wid] = part;
    __syncthreads();
    if (tid == 0) {
        float t = 0.0f;
#pragma unroll
        for (int w = 0; w < 8; w++) t += wsum[w];
        d_pfin[bid] = t;
    }
}

// ---------------- 6) final deterministic reduce ------------------------------
__global__ void finalreduce(float* __restrict__ out) {
    __shared__ float rb[256];
    int tid = threadIdx.x;
    rb[tid] = d_pfin[tid];
    __syncthreads();
    for (int st = 128; st; st >>= 1) {
        if (tid < st) rb[tid] += rb[tid + st];
        __syncthreads();
    }
    if (tid == 0) out[0] = 2.0f * rb[0];
}

// ---------------- launch -----------------------------------------------------
extern "C" void kernel_launch(void* const* d_in, const int* in_sizes, int n_in,
                              void* d_out, int out_size) {
    const float* enc = (const float*)d_in[0];
    const int*   t   = (const int*)d_in[2];
    float* out = (float*)d_out;

    part_kernel<<<1, 1024>>>(t);
    gather_kernel<<<dim3(N_TOTAL, S_STEPS), 64>>>(enc);
    gemm_kernel<<<dim3(16, 16, S_STEPS), 256>>>();
    reduce_stats<<<S_STEPS, 256>>>();
    sink_cluster<<<256, 256>>>();
    finalreduce<<<1, 256>>>(out);
}

// round 16
// speedup vs baseline: 1.2273x; 1.0404x over previous
#include <cuda_runtime.h>
#include <cuda_fp16.h>
#include <cuda_bf16.h>
#include <cstdint>

#define N_TOTAL 2048
#define S_STEPS 32
#define DIM 256
#define PER_TS 1507328      // >= rows_max * rsU_max (rsU <= 1152)
#define ZSTRIDE 2056
#define NCHMAX 9            // max column chunks of 128 (rsU <= 1152)

// ---------------- scratch (device globals; no dynamic allocation) ------------
__device__ __align__(16) __half d_Mh[(size_t)S_STEPS * PER_TS];
__device__ __align__(16) __half d_Kh[(size_t)S_STEPS * PER_TS];
__device__ __align__(16) __nv_bfloat16 d_Xhi[(size_t)S_STEPS * N_TOTAL * DIM];
__device__ float d_norm[S_STEPS * N_TOTAL];
__device__ int   d_it[N_TOTAL], d_ic[N_TOTAL];
__device__ int   d_nt, d_nc;
__device__ float d_p;
__device__ float d_lam[S_STEPS], d_delta[S_STEPS];
__device__ __align__(16) float d_u[S_STEPS * ZSTRIDE];
__device__ __align__(16) float d_cpart[(size_t)S_STEPS * 8 * 1152];
__device__ float d_pmax[S_STEPS * 256];
__device__ float d_psum[S_STEPS * 256];
__device__ float d_pfin[256];

// ---------------- fast exp (Cephes, FMA pipe; args in [-8, 0]) ---------------
__device__ __forceinline__ float fexpf_(float x) {
    float z = fmaf(x, 1.4426950408889634f, 12582912.0f);
    float n = z - 12582912.0f;
    float r = fmaf(n, -0.693359375f, x);
    r = fmaf(n, 2.12194440e-4f, r);
    float p = 1.9875691500e-4f;
    p = fmaf(p, r, 1.3981999507e-3f);
    p = fmaf(p, r, 8.3334519073e-3f);
    p = fmaf(p, r, 4.1665795894e-2f);
    p = fmaf(p, r, 1.6666665459e-1f);
    p = fmaf(p, r, 5.0000001201e-1f);
    float e = fmaf(r * r, p, r) + 1.0f;
    int ni = (int)n;
    return __int_as_float(__float_as_int(e) + (ni << 23));
}

__device__ __forceinline__ uint32_t smem_u32(const void* p) {
    uint32_t a;
    asm("{ .reg .u64 t; cvta.to.shared.u64 t, %1; cvt.u32.u64 %0, t; }" : "=r"(a) : "l"(p));
    return a;
}

// 4 halves -> float4
__device__ __forceinline__ float4 h4_f4(uint2 w) {
    float2 a = __half22float2(*reinterpret_cast<__half2*>(&w.x));
    float2 b = __half22float2(*reinterpret_cast<__half2*>(&w.y));
    return make_float4(a.x, a.y, b.x, b.y);
}

#define CLUSTER_SYNC() do { \
    asm volatile("barrier.cluster.arrive.aligned;" ::: "memory"); \
    asm volatile("barrier.cluster.wait.aligned;" ::: "memory"); } while (0)

#define LDSM4(R, addr) \
    asm volatile("ldmatrix.sync.aligned.m8n8.x4.shared.b16 {%0,%1,%2,%3}, [%4];" \
        : "=r"((R)[0]), "=r"((R)[1]), "=r"((R)[2]), "=r"((R)[3]) : "r"(addr))

#define MMA_BF16(C, A, b0_, b1_) \
    asm volatile("mma.sync.aligned.m16n8k16.row.col.f32.bf16.bf16.f32 " \
        "{%0,%1,%2,%3}, {%4,%5,%6,%7}, {%8,%9}, {%0,%1,%2,%3};" \
        : "+f"((C)[0]), "+f"((C)[1]), "+f"((C)[2]), "+f"((C)[3]) \
        : "r"((A)[0]), "r"((A)[1]), "r"((A)[2]), "r"((A)[3]), "r"(b0_), "r"(b1_))

#define CP_ASYNC16(smaddr, gptr, srcsz) \
    asm volatile("cp.async.cg.shared.global [%0], [%1], 16, %2;" \
        :: "r"(smaddr), "l"(gptr), "r"(srcsz))

// ---------------- 1) partition indices (deterministic, single block) ---------
__global__ void part_kernel(const int* __restrict__ t) {
    __shared__ int wcntT[64];
    __shared__ int wprefT[64], wprefC[64];
    int tid = threadIdx.x, lane = tid & 31, wid = tid >> 5;
    for (int c = wid; c < 64; c += 32) {
        int e = c * 32 + lane;
        int f = t[e] > 0;
        unsigned m = __ballot_sync(0xffffffffu, f);
        if (lane == 0) wcntT[c] = __popc(m);
    }
    __syncthreads();
    if (tid == 0) {
        int aT = 0;
        for (int c = 0; c < 64; c++) {
            wprefT[c] = aT;
            wprefC[c] = c * 32 - aT;
            aT += wcntT[c];
        }
        d_nt = aT;
        d_nc = N_TOTAL - aT;
        d_p  = (float)aT / (float)N_TOTAL;
    }
    __syncthreads();
    for (int c = wid; c < 64; c += 32) {
        int e = c * 32 + lane;
        int f = t[e] > 0;
        unsigned m  = __ballot_sync(0xffffffffu, f);
        unsigned lt = ((1u << lane) - 1u);
        if (f) d_it[wprefT[c] + __popc(m & lt)]  = e;
        else   d_ic[wprefC[c] + __popc(~m & lt)] = e;
    }
}

// ---------------- 2) gather rows -> bf16 + fp32 row norms --------------------
// grid (N_TOTAL, S), 64 threads
__global__ void gather_kernel(const float* __restrict__ enc) {
    int r = blockIdx.x, s = blockIdx.y, tid = threadIdx.x;
    int nt = d_nt;
    int src = (r < nt) ? d_it[r] : d_ic[r - nt];
    const float4* in = (const float4*)(enc + ((size_t)src * S_STEPS + s) * DIM);
    float4 v = in[tid];

    __nv_bfloat162 h01 = {__float2bfloat16_rn(v.x), __float2bfloat16_rn(v.y)};
    __nv_bfloat162 h23 = {__float2bfloat16_rn(v.z), __float2bfloat16_rn(v.w)};
    size_t base = ((size_t)s * N_TOTAL + r) * DIM + (size_t)tid * 4;
    uint2 hv = { *(unsigned*)&h01, *(unsigned*)&h23 };
    *(uint2*)(d_Xhi + base) = hv;

    float nrm = v.x * v.x + v.y * v.y + v.z * v.z + v.w * v.w;
    for (int o = 16; o; o >>= 1) nrm += __shfl_down_sync(0xffffffffu, nrm, o);
    __shared__ float sn[2];
    if ((tid & 31) == 0) sn[tid >> 5] = nrm;
    __syncthreads();
    if (tid == 0) d_norm[s * N_TOTAL + r] = sn[0] + sn[1];
}

// ---------------- 3) bf16 GEMM w/ cp.async double buffer ---------------------
// grid (16,16,S), 256 threads (8 warps: 2 m x 4 n), CTA tile 128x128
__global__ void __launch_bounds__(256, 2) gemm_kernel() {
    __shared__ __align__(16) unsigned char sm[41984];
    float* rbuf = (float*)(sm + 40960);

    int tid = threadIdx.x, lane = tid & 31, wid = tid >> 5;
    int wm = wid >> 2, wn = wid & 3;
    int s = blockIdx.z;
    int nt = d_nt, nc = d_nc;
    int i0 = blockIdx.y * 128, j0 = blockIdx.x * 128;
    int pidx = s * 256 + blockIdx.y * 16 + blockIdx.x;

    if (i0 >= nt || j0 >= nc) {
        if (tid == 0) { d_pmax[pidx] = 0.0f; d_psum[pidx] = 0.0f; }
        return;
    }

    uint32_t sb = smem_u32(sm);
    size_t Xbase = (size_t)s * N_TOTAL * DIM;

    int rowA[2], segA[2];
    bool va[2], vb[2];
    const __nv_bfloat16 *gA[2], *gB[2];
#pragma unroll
    for (int h = 0; h < 2; h++) {
        int idx = tid + h * 256;
        rowA[h] = idx >> 2; segA[h] = idx & 3;
        va[h] = (i0 + rowA[h]) < nt;
        vb[h] = (j0 + rowA[h]) < nc;
        int ra = va[h] ? (i0 + rowA[h]) : 0;
        int rb = vb[h] ? (j0 + rowA[h]) : 0;
        gA[h] = d_Xhi + Xbase + (size_t)ra * DIM + segA[h] * 8;
        gB[h] = d_Xhi + Xbase + (size_t)(nt + rb) * DIM + segA[h] * 8;
    }

    float c[4][4][4];
#pragma unroll
    for (int a = 0; a < 4; a++)
#pragma unroll
        for (int b = 0; b < 4; b++)
#pragma unroll
            for (int q = 0; q < 4; q++) c[a][b][q] = 0.0f;

    auto issue = [&](int chunk) {
        int k0 = chunk * 32;
        uint32_t bufo = (uint32_t)(chunk & 1) * 20480u;
#pragma unroll
        for (int h = 0; h < 2; h++) {
            uint32_t doff = (uint32_t)rowA[h] * 80 + (uint32_t)segA[h] * 16;
            CP_ASYNC16(sb + bufo + doff, gA[h] + k0, va[h] ? 16 : 0);
            CP_ASYNC16(sb + bufo + 10240 + doff, gB[h] + k0, vb[h] ? 16 : 0);
        }
        asm volatile("cp.async.commit_group;");
    };

    issue(0);

    for (int chunk = 0; chunk < 8; chunk++) {
        if (chunk < 7) {
            issue(chunk + 1);
            asm volatile("cp.async.wait_group 1;");
        } else {
            asm volatile("cp.async.wait_group 0;");
        }
        __syncthreads();

        uint32_t bufo = (uint32_t)(chunk & 1) * 20480u;
#pragma unroll
        for (int ks = 0; ks < 32; ks += 16) {
            uint32_t colb = (uint32_t)(ks + ((lane >> 4) << 3)) * 2;
            uint32_t ah[4][4], bh2[2][4];
#pragma unroll
            for (int mt = 0; mt < 4; mt++) {
                uint32_t addr = sb + bufo + (uint32_t)(wm * 64 + mt * 16 + (lane & 15)) * 80 + colb;
                LDSM4(ah[mt], addr);
            }
#pragma unroll
            for (int pp = 0; pp < 2; pp++) {
                uint32_t addr = sb + bufo + 10240 + (uint32_t)(wn * 32 + pp * 16 + (lane & 15)) * 80 + colb;
                LDSM4(bh2[pp], addr);
            }
#pragma unroll
            for (int mt = 0; mt < 4; mt++)
#pragma unroll
                for (int nn = 0; nn < 4; nn++) {
                    int pp = nn >> 1, od = nn & 1;
                    MMA_BF16(c[mt][nn], ah[mt], bh2[pp][od], bh2[pp][2 + od]);
                }
        }
        __syncthreads();
    }

    float* nbs = (float*)sm;
    for (int q = tid; q < 128; q += 256)
        nbs[q] = (j0 + q < nc) ? d_norm[s * N_TOTAL + nt + j0 + q] : 0.0f;
    __syncthreads();

    int rsU = (nc + 128) & ~127;
    float lmax = 0.0f, lsum = 0.0f;
#pragma unroll
    for (int mt = 0; mt < 4; mt++) {
        int gi0 = i0 + wm * 64 + mt * 16 + (lane >> 2);
        int gi1 = gi0 + 8;
        float na0 = (gi0 < nt) ? d_norm[s * N_TOTAL + gi0] : 0.0f;
        float na1 = (gi1 < nt) ? d_norm[s * N_TOTAL + gi1] : 0.0f;
#pragma unroll
        for (int nn = 0; nn < 4; nn++) {
            int lj = wn * 32 + nn * 8 + (lane & 3) * 2;
            int gj = j0 + lj;
            float nb0 = nbs[lj], nb1 = nbs[lj + 1];
            bool vj0 = gj < nc, vj1 = (gj + 1) < nc;
            float m00 = na0 + nb0 - 2.0f * c[mt][nn][0];
            float m01 = na0 + nb1 - 2.0f * c[mt][nn][1];
            float m10 = na1 + nb0 - 2.0f * c[mt][nn][2];
            float m11 = na1 + nb1 - 2.0f * c[mt][nn][3];
            if (gi0 < nt) {
                __half* Mr = d_Mh + (size_t)s * PER_TS + (size_t)gi0 * rsU + gj;
                if (vj0) { lmax = fmaxf(lmax, m00); lsum += m00; }
                if (vj1) { lmax = fmaxf(lmax, m01); lsum += m01; }
                if (vj0 && vj1) *(__half2*)Mr = __floats2half2_rn(m00, m01);
                else if (vj0)   *Mr = __float2half_rn(m00);
            }
            if (gi1 < nt) {
                __half* Mr = d_Mh + (size_t)s * PER_TS + (size_t)gi1 * rsU + gj;
                if (vj0) { lmax = fmaxf(lmax, m10); lsum += m10; }
                if (vj1) { lmax = fmaxf(lmax, m11); lsum += m11; }
                if (vj0 && vj1) *(__half2*)Mr = __floats2half2_rn(m10, m11);
                else if (vj0)   *Mr = __float2half_rn(m10);
            }
        }
    }

    rbuf[tid] = lmax; __syncthreads();
    for (int st = 128; st; st >>= 1) {
        if (tid < st) rbuf[tid] = fmaxf(rbuf[tid], rbuf[tid + st]);
        __syncthreads();
    }
    if (tid == 0) d_pmax[pidx] = rbuf[0];
    __syncthreads();
    rbuf[tid] = lsum; __syncthreads();
    for (int st = 128; st; st >>= 1) {
        if (tid < st) rbuf[tid] += rbuf[tid + st];
        __syncthreads();
    }
    if (tid == 0) d_psum[pidx] = rbuf[0];
}

// ---------------- 4) per-timestep stats --------------------------------------
__global__ void reduce_stats() {
    __shared__ float rb[256];
    int s = blockIdx.x, tid = threadIdx.x;
    float mv = d_pmax[s * 256 + tid];
    float sv = d_psum[s * 256 + tid];
    rb[tid] = mv; __syncthreads();
    for (int st = 128; st; st >>= 1) {
        if (tid < st) rb[tid] = fmaxf(rb[tid], rb[tid + st]);
        __syncthreads();
    }
    float mx = rb[0];
    __syncthreads();
    rb[tid] = sv; __syncthreads();
    for (int st = 128; st; st >>= 1) {
        if (tid < st) rb[tid] += rb[tid + st];
        __syncthreads();
    }
    if (tid == 0) {
        d_delta[s] = mx;
        d_lam[s] = ((float)d_nt * (float)d_nc) / rb[0];
    }
}

// ---------------- 5) persistent fused Sinkhorn: 32 clusters x 8 CTAs x 256 ----
// Paired-row fused pass: two independent dependency chains per warp iteration.
__global__ void __cluster_dims__(8, 1, 1) __launch_bounds__(256, 2) sink_cluster() {
    __shared__ float redf[8 * 1160];
    __shared__ float wsum[8];
    __shared__ __align__(16) float svec[1156];
    int bid = blockIdx.x;
    int s = bid >> 3, cr = bid & 7;
    int tid = threadIdx.x, lane = tid & 31, wid = tid >> 5; // 8 warps
    int nt = d_nt, nc = d_nc, ntp = nt + 1;
    int rsU = (nc + 128) & ~127;
    int nch = rsU >> 7;
    float lam = d_lam[s], delta = d_delta[s], p = d_p;
    float an = p / (float)nt, ap = 1.0f - p;
    float bn = (1.0f - p) / (float)nc, bp = p;
    __half* Mb = d_Mh + (size_t)s * PER_TS;
    __half* Kb = d_Kh + (size_t)s * PER_TS;
    float* ub = d_u + s * ZSTRIDE;
    float* cp = d_cpart + (size_t)s * 8 * 1152;

    // ---- Phase A: build K fp16 + M pads on private row strip ----
    int H = (ntp + 7) >> 3;
    int r0 = cr * H;
    int r1 = min(ntp, r0 + H);
    float kpad = fexpf_(-lam * delta) + 1e-6f;
    float kcorner = 1.0f + 1e-6f;
    for (int r = r0; r < r1; r++) {
        __half* Mw = Mb + (size_t)r * rsU;
        __half* Kr = Kb + (size_t)r * rsU;
        for (int c = tid * 2; c < rsU; c += 512) {
            float kk[2];
#pragma unroll
            for (int q = 0; q < 2; q++) {
                int cc = c + q;
                float kv;
                if (r < nt) {
                    if (cc < nc) {
                        kv = fexpf_(-lam * __half2float(Mw[cc])) + 1e-6f;
                    } else if (cc == nc) {
                        kv = kpad; Mw[cc] = __float2half_rn(delta);
                    } else {
                        kv = 0.0f; Mw[cc] = __float2half_rn(0.0f);
                    }
                } else {
                    if (cc < nc) { kv = kpad; Mw[cc] = __float2half_rn(delta); }
                    else if (cc == nc) { kv = kcorner; Mw[cc] = __float2half_rn(0.0f); }
                    else { kv = 0.0f; Mw[cc] = __float2half_rn(0.0f); }
                }
                kk[q] = kv;
            }
            __half2 h2 = __floats2half2_rn(kk[0], kk[1]);
            *(unsigned*)(Kr + c) = *(unsigned*)&h2;
        }
    }
    __syncthreads();   // K strip is CTA-private; no cluster sync needed

    // ---- fused pass: mode 0 = u is 'a' (init colsum); mode 1 = full step ----
    auto fused_pass = [&](int mode) {
        float acc[NCHMAX][4];
#pragma unroll
        for (int c = 0; c < NCHMAX; c++) {
            acc[c][0] = 0.f; acc[c][1] = 0.f; acc[c][2] = 0.f; acc[c][3] = 0.f;
        }
        for (int i = r0 + wid; i < r1; i += 16) {
            int i2 = i + 8;
            bool has2 = i2 < r1;
            const __half* Kr1 = Kb + (size_t)i * rsU;
            const __half* Kr2 = Kb + (size_t)(has2 ? i2 : i) * rsU;
            uint2 kw1[NCHMAX], kw2[NCHMAX];
            float d1 = 0.0f, d2 = 0.0f;
#pragma unroll
            for (int c = 0; c < NCHMAX; c++) {
                if (c < nch) {
                    int jj = c * 128 + lane * 4;
                    kw1[c] = *(const uint2*)(Kr1 + jj);
                    kw2[c] = *(const uint2*)(Kr2 + jj);
                }
            }
            if (mode) {
#pragma unroll
                for (int c = 0; c < NCHMAX; c++) {
                    if (c < nch) {
                        int jj = c * 128 + lane * 4;
                        float4 zv = *(const float4*)(svec + jj);
                        float4 k1 = h4_f4(kw1[c]);
                        float4 k2 = h4_f4(kw2[c]);
                        d1 = fmaf(k1.x, zv.x, d1); d1 = fmaf(k1.y, zv.y, d1);
                        d1 = fmaf(k1.z, zv.z, d1); d1 = fmaf(k1.w, zv.w, d1);
                        d2 = fmaf(k2.x, zv.x, d2); d2 = fmaf(k2.y, zv.y, d2);
                        d2 = fmaf(k2.z, zv.z, d2); d2 = fmaf(k2.w, zv.w, d2);
                    }
                }
#pragma unroll
                for (int o = 16; o; o >>= 1) {
                    d1 += __shfl_xor_sync(0xffffffffu, d1, o);
                    d2 += __shfl_xor_sync(0xffffffffu, d2, o);
                }
            }
            float ui1, ui2;
            if (mode) {
                ui1 = ((i < nt) ? an : ap) / d1;
                ui2 = has2 ? (((i2 < nt) ? an : ap) / d2) : 0.0f;
                if (lane == 0) {
                    __stcg(ub + i, ui1);
                    if (has2) __stcg(ub + i2, ui2);
                }
            } else {
                ui1 = (i < nt) ? an : ap;
                ui2 = has2 ? ((i2 < nt) ? an : ap) : 0.0f;
            }
#pragma unroll
            for (int c = 0; c < NCHMAX; c++) {
                if (c < nch) {
                    float4 k1 = h4_f4(kw1[c]);
                    float4 k2 = h4_f4(kw2[c]);
                    acc[c][0] = fmaf(ui1, k1.x, fmaf(ui2, k2.x, acc[c][0]));
                    acc[c][1] = fmaf(ui1, k1.y, fmaf(ui2, k2.y, acc[c][1]));
                    acc[c][2] = fmaf(ui1, k1.z, fmaf(ui2, k2.z, acc[c][2]));
                    acc[c][3] = fmaf(ui1, k1.w, fmaf(ui2, k2.w, acc[c][3]));
                }
            }
        }
        // merge 8 warp-private partials -> CTA partial -> global cpart
#pragma unroll
        for (int c = 0; c < NCHMAX; c++) {
            if (c < nch)
                *(float4*)&redf[wid * 1160 + c * 128 + lane * 4] = *(float4*)acc[c];
        }
        __syncthreads();
        for (int j = tid; j < rsU; j += 256) {
            float t = redf[j];
#pragma unroll
            for (int w = 1; w < 8; w++) t += redf[w * 1160 + j];
            __stcg(cp + (size_t)cr * 1152 + j, t);
        }
    };

    // rebuild full z locally in smem from the 8 CTA partials
    auto build_z = [&]() {
        for (int j = tid; j < rsU; j += 256) {
            float t = 0.0f;
#pragma unroll
            for (int c2 = 0; c2 < 8; c2++) t += __ldcg(cp + (size_t)c2 * 1152 + j);
            svec[j] = (j < nc) ? (bn / t) : ((j == nc) ? (bp / t) : 0.0f);
        }
        __syncthreads();
    };

    // pass 0: colsum with u = a
    fused_pass(0);
    CLUSTER_SYNC();
    build_z();

    // 20 fused iterations; after the 20th, svec holds v = b/(K^T u_final)
    for (int it = 0; it < 20; it++) {
        fused_pass(1);
        CLUSTER_SYNC();
        build_z();
    }

    // ---- finalsum on row strip: sum_i u_i * sum_j K_ij M_ij v_j ----
    float part = 0.0f;
    for (int i = r0 + wid; i < r1; i += 8) {
        const __half* Kr = Kb + (size_t)i * rsU;
        const __half* Mr = Mb + (size_t)i * rsU;
        float a1 = 0.0f;
#pragma unroll
        for (int c = 0; c < NCHMAX; c++) {
            if (c < nch) {
                int jj = c * 128 + lane * 4;
                float4 kf = h4_f4(*(const uint2*)(Kr + jj));
                float4 mf = h4_f4(*(const uint2*)(Mr + jj));
                float4 zv = *(const float4*)(svec + jj);
                a1 = fmaf(kf.x * mf.x, zv.x, a1);
                a1 = fmaf(kf.y * mf.y, zv.y, a1);
                a1 = fmaf(kf.z * mf.z, zv.z, a1);
                a1 = fmaf(kf.w * mf.w, zv.w, a1);
            }
        }
#pragma unroll
        for (int o = 16; o; o >>= 1) a1 += __shfl_down_sync(0xffffffffu, a1, o);
        if (lane == 0) part = fmaf(__ldcg(ub + i), a1, part);
    }
    if (lane == 0) wsum[wid] = part;
    __syncthreads();
    if (tid == 0) {
        float t = 0.0f;
#pragma unroll
        for (int w = 0; w < 8; w++) t += wsum[w];
        d_pfin[bid] = t;
    }
}

// ---------------- 6) final deterministic reduce ------------------------------
__global__ void finalreduce(float* __restrict__ out) {
    __shared__ float rb[256];
    int tid = threadIdx.x;
    rb[tid] = d_pfin[tid];
    __syncthreads();
    for (int st = 128; st; st >>= 1) {
        if (tid < st) rb[tid] += rb[tid + st];
        __syncthreads();
    }
    if (tid == 0) out[0] = 2.0f * rb[0];
}

// ---------------- launch -----------------------------------------------------
extern "C" void kernel_launch(void* const* d_in, const int* in_sizes, int n_in,
                              void* d_out, int out_size) {
    const float* enc = (const float*)d_in[0];
    const int*   t   = (const int*)d_in[2];
    float* out = (float*)d_out;

    part_kernel<<<1, 1024>>>(t);
    gather_kernel<<<dim3(N_TOTAL, S_STEPS), 64>>>(enc);
    gemm_kernel<<<dim3(16, 16, S_STEPS), 256>>>();
    reduce_stats<<<S_STEPS, 256>>>();
    sink_cluster<<<256, 256>>>();
    finalreduce<<<1, 256>>>(out);
}